// round 1
// baseline (speedup 1.0000x reference)
#include <cuda_runtime.h>
#include <cstdint>
#include <math.h>

#define NEXP 16
#define TOPK 4
#define HDIM 2048
#define IDIM 2048
#define TWO_I 4096
#define TMAX 4096
#define ALPHA 1.702f
#define LIMIT 7.0f

#define BM 128
#define BN 128
#define BK 16
#define PADA 20    // 20 floats = 80B, multiple of 16B, conflict-free A frag loads
#define PADB 136   // 136 floats = 544B, multiple of 16B, conflict-free B frag loads

// routing scratch (device globals: allocation-free kernel_launch)
__device__ int   g_cnt[NEXP];
__device__ int   g_tok[NEXP * TMAX];
__device__ float g_wt[NEXP * TMAX];
__device__ float g_act[134217728];   // NEXP * TMAX * IDIM fp32 activations

// ---------------- helpers ----------------

__device__ __forceinline__ uint32_t f2tf32(float x) {
  uint32_t r;
  asm("cvt.rna.tf32.f32 %0, %1;" : "=r"(r) : "f"(x));
  return r;
}

__device__ __forceinline__ void cp16(float* dst, const float* src, bool pred) {
  uint32_t d = (uint32_t)__cvta_generic_to_shared(dst);
  int sz = pred ? 16 : 0;
  asm volatile("cp.async.cg.shared.global [%0], [%1], 16, %2;" :: "r"(d), "l"(src), "r"(sz));
}

__device__ __forceinline__ void cp_commit() { asm volatile("cp.async.commit_group;"); }

__device__ __forceinline__ void mma_tf32(float* c, const uint32_t* a, const uint32_t* b) {
  asm volatile(
      "mma.sync.aligned.m16n8k8.row.col.f32.tf32.tf32.f32 "
      "{%0,%1,%2,%3}, {%4,%5,%6,%7}, {%8,%9}, {%0,%1,%2,%3};"
      : "+f"(c[0]), "+f"(c[1]), "+f"(c[2]), "+f"(c[3])
      : "r"(a[0]), "r"(a[1]), "r"(a[2]), "r"(a[3]), "r"(b[0]), "r"(b[1]));
}

// ---------------- router ----------------

__global__ void zero_cnt_kernel() {
  if (threadIdx.x < NEXP) g_cnt[threadIdx.x] = 0;
}

__global__ __launch_bounds__(256) void router_kernel(const float* __restrict__ x,
                                                     const float* __restrict__ rw,
                                                     const float* __restrict__ rb) {
  int warp = threadIdx.x >> 5, lane = threadIdx.x & 31;
  int t = blockIdx.x * 8 + warp;
  float acc[NEXP];
#pragma unroll
  for (int e = 0; e < NEXP; e++) acc[e] = 0.f;
  const float* xr = x + (size_t)t * HDIM;
  for (int h = lane; h < HDIM; h += 32) {
    float xv = xr[h];
#pragma unroll
    for (int e = 0; e < NEXP; e++) acc[e] = fmaf(xv, rw[e * HDIM + h], acc[e]);
  }
#pragma unroll
  for (int e = 0; e < NEXP; e++) {
#pragma unroll
    for (int o = 16; o > 0; o >>= 1) acc[e] += __shfl_xor_sync(0xffffffffu, acc[e], o);
  }
  if (lane == 0) {
    float v[NEXP];
#pragma unroll
    for (int e = 0; e < NEXP; e++) v[e] = acc[e] + rb[e];
    int ids[TOPK]; float vals[TOPK];
#pragma unroll
    for (int j = 0; j < TOPK; j++) {
      float best = -1e30f; int bi = 0;
#pragma unroll
      for (int e = 0; e < NEXP; e++)
        if (v[e] > best) { best = v[e]; bi = e; }
      ids[j] = bi; vals[j] = best; v[bi] = -1e30f;
    }
    float m = vals[0], s = 0.f, w[TOPK];
#pragma unroll
    for (int j = 0; j < TOPK; j++) { w[j] = expf(vals[j] - m); s += w[j]; }
    float inv = 1.f / s;
#pragma unroll
    for (int j = 0; j < TOPK; j++) {
      int e = ids[j];
      int p = atomicAdd(&g_cnt[e], 1);
      g_tok[e * TMAX + p] = t;
      g_wt[e * TMAX + p]  = w[j] * inv;
    }
  }
}

// ---------------- GEMM1: X @ w1[e] + b1 -> clipped GLU -> g_act ----------------

__device__ __forceinline__ void g1_load(const float* __restrict__ X, const float* __restrict__ w1e,
                                        float* As, float* Bg, float* Bu,
                                        int tid, int s, int kb, int n0, int tok0, int tok1) {
  int row = tid >> 2, c4 = (tid & 3) << 2;
  const float* srcA = X + (size_t)(tok0 < 0 ? 0 : tok0) * HDIM + kb * BK + c4;
  cp16(&As[(s * BM + row) * PADA + c4], srcA, tok0 >= 0);
  srcA = X + (size_t)(tok1 < 0 ? 0 : tok1) * HDIM + kb * BK + c4;
  cp16(&As[(s * BM + row + 64) * PADA + c4], srcA, tok1 >= 0);
#pragma unroll
  for (int i = 0; i < 2; i++) {
    int idx = tid + i * 256;
    int brow = idx >> 5, c = (idx & 31) << 2;
    const float* srcg = w1e + (size_t)(kb * BK + brow) * TWO_I + n0 + c;
    cp16(&Bg[(s * BK + brow) * PADB + c], srcg, true);
    cp16(&Bu[(s * BK + brow) * PADB + c], srcg + IDIM, true);
  }
}

__global__ __launch_bounds__(256, 1) void gemm1_kernel(const float* __restrict__ X,
                                                       const float* __restrict__ w1,
                                                       const float* __restrict__ b1) {
  int e = blockIdx.z;
  int cnt = g_cnt[e];
  int m0 = blockIdx.y * BM;
  if (m0 >= cnt) return;
  int n0 = blockIdx.x * BN;

  extern __shared__ float smem[];
  float* As = smem;                       // 2*128*20
  float* Bg = As + 2 * BM * PADA;         // 2*16*136
  float* Bu = Bg + 2 * BK * PADB;         // 2*16*136
  int* toks = (int*)(Bu + 2 * BK * PADB); // 128

  int tid = threadIdx.x;
  if (tid < BM) {
    int r = m0 + tid;
    toks[tid] = (r < cnt) ? g_tok[e * TMAX + r] : -1;
  }
  __syncthreads();

  int arow = tid >> 2;
  int tok0 = toks[arow], tok1 = toks[arow + 64];

  const float* w1e = w1 + (size_t)e * HDIM * TWO_I;

  int warp = tid >> 5, lane = tid & 31;
  int wm = (warp >> 1) * 32, wn = (warp & 1) * 64;
  int g = lane >> 2, tq = lane & 3;

  float cg[2][8][4], cu[2][8][4];
#pragma unroll
  for (int mi = 0; mi < 2; mi++)
#pragma unroll
    for (int ni = 0; ni < 8; ni++)
#pragma unroll
      for (int q = 0; q < 4; q++) { cg[mi][ni][q] = 0.f; cu[mi][ni][q] = 0.f; }

  g1_load(X, w1e, As, Bg, Bu, tid, 0, 0, n0, tok0, tok1);
  cp_commit();

  const int NK = HDIM / BK;
  for (int kb = 0; kb < NK; kb++) {
    int s = kb & 1;
    if (kb + 1 < NK) {
      g1_load(X, w1e, As, Bg, Bu, tid, s ^ 1, kb + 1, n0, tok0, tok1);
      cp_commit();
      asm volatile("cp.async.wait_group 1;");
    } else {
      asm volatile("cp.async.wait_group 0;");
    }
    __syncthreads();
#pragma unroll
    for (int kk = 0; kk < 2; kk++) {
      uint32_t af[2][4];
#pragma unroll
      for (int mi = 0; mi < 2; mi++) {
        const float* ab = &As[(s * BM + wm + mi * 16) * PADA + kk * 8];
        af[mi][0] = f2tf32(ab[g * PADA + tq]);
        af[mi][1] = f2tf32(ab[(g + 8) * PADA + tq]);
        af[mi][2] = f2tf32(ab[g * PADA + tq + 4]);
        af[mi][3] = f2tf32(ab[(g + 8) * PADA + tq + 4]);
      }
#pragma unroll
      for (int ni = 0; ni < 8; ni++) {
        int col = wn + ni * 8 + g;
        const float* bgp = &Bg[(s * BK + kk * 8 + tq) * PADB + col];
        const float* bup = &Bu[(s * BK + kk * 8 + tq) * PADB + col];
        uint32_t bfg[2], bfu[2];
        bfg[0] = f2tf32(bgp[0]);
        bfg[1] = f2tf32(bgp[4 * PADB]);
        bfu[0] = f2tf32(bup[0]);
        bfu[1] = f2tf32(bup[4 * PADB]);
#pragma unroll
        for (int mi = 0; mi < 2; mi++) {
          mma_tf32(cg[mi][ni], af[mi], bfg);
          mma_tf32(cu[mi][ni], af[mi], bfu);
        }
      }
    }
    __syncthreads();
  }

  const float* b1e = b1 + (size_t)e * TWO_I;
#pragma unroll
  for (int mi = 0; mi < 2; mi++) {
#pragma unroll
    for (int rr = 0; rr < 2; rr++) {
      int r = m0 + wm + mi * 16 + rr * 8 + g;
      if (r >= cnt) continue;
      float* ar = g_act + ((size_t)e * TMAX + r) * IDIM;
#pragma unroll
      for (int ni = 0; ni < 8; ni++) {
        int c = n0 + wn + ni * 8 + (tq << 1);
#pragma unroll
        for (int q = 0; q < 2; q++) {
          float gv = cg[mi][ni][rr * 2 + q] + b1e[c + q];
          float uv = cu[mi][ni][rr * 2 + q] + b1e[IDIM + c + q];
          gv = fminf(gv, LIMIT);
          uv = fminf(fmaxf(uv, -LIMIT), LIMIT);
          float sig = 1.f / (1.f + expf(-ALPHA * gv));
          ar[c + q] = (uv + 1.f) * gv * sig;
        }
      }
    }
  }
}

// ---------------- GEMM2: act @ w2[e] + b2 -> weighted scatter-add ----------------

__device__ __forceinline__ void g2_load(const float* __restrict__ w2e,
                                        float* As, float* Bs,
                                        int tid, int s, int kb, int n0, int e, int m0, int cnt) {
  int row = tid >> 2, c4 = (tid & 3) << 2;
  const float* srcA = g_act + ((size_t)e * TMAX + m0 + row) * IDIM + kb * BK + c4;
  cp16(&As[(s * BM + row) * PADA + c4], srcA, (m0 + row) < cnt);
  srcA = g_act + ((size_t)e * TMAX + m0 + row + 64) * IDIM + kb * BK + c4;
  cp16(&As[(s * BM + row + 64) * PADA + c4], srcA, (m0 + row + 64) < cnt);
#pragma unroll
  for (int i = 0; i < 2; i++) {
    int idx = tid + i * 256;
    int brow = idx >> 5, c = (idx & 31) << 2;
    const float* srcB = w2e + (size_t)(kb * BK + brow) * HDIM + n0 + c;
    cp16(&Bs[(s * BK + brow) * PADB + c], srcB, true);
  }
}

__global__ __launch_bounds__(256, 1) void gemm2_kernel(const float* __restrict__ w2,
                                                       const float* __restrict__ b2,
                                                       float* __restrict__ out) {
  int e = blockIdx.z;
  int cnt = g_cnt[e];
  int m0 = blockIdx.y * BM;
  if (m0 >= cnt) return;
  int n0 = blockIdx.x * BN;

  extern __shared__ float smem[];
  float* As = smem;                        // 2*128*20
  float* Bs = As + 2 * BM * PADA;          // 2*16*136
  int* toks = (int*)(Bs + 2 * BK * PADB);  // 128
  float* wts = (float*)(toks + BM);        // 128

  int tid = threadIdx.x;
  if (tid < BM) {
    int r = m0 + tid;
    bool v = r < cnt;
    toks[tid] = v ? g_tok[e * TMAX + r] : 0;
    wts[tid]  = v ? g_wt[e * TMAX + r] : 0.f;
  }
  __syncthreads();

  const float* w2e = w2 + (size_t)e * IDIM * HDIM;

  int warp = tid >> 5, lane = tid & 31;
  int wm = (warp >> 1) * 32, wn = (warp & 1) * 64;
  int g = lane >> 2, tq = lane & 3;

  float cc[2][8][4];
#pragma unroll
  for (int mi = 0; mi < 2; mi++)
#pragma unroll
    for (int ni = 0; ni < 8; ni++)
#pragma unroll
      for (int q = 0; q < 4; q++) cc[mi][ni][q] = 0.f;

  g2_load(w2e, As, Bs, tid, 0, 0, n0, e, m0, cnt);
  cp_commit();

  const int NK = IDIM / BK;
  for (int kb = 0; kb < NK; kb++) {
    int s = kb & 1;
    if (kb + 1 < NK) {
      g2_load(w2e, As, Bs, tid, s ^ 1, kb + 1, n0, e, m0, cnt);
      cp_commit();
      asm volatile("cp.async.wait_group 1;");
    } else {
      asm volatile("cp.async.wait_group 0;");
    }
    __syncthreads();
#pragma unroll
    for (int kk = 0; kk < 2; kk++) {
      uint32_t af[2][4];
#pragma unroll
      for (int mi = 0; mi < 2; mi++) {
        const float* ab = &As[(s * BM + wm + mi * 16) * PADA + kk * 8];
        af[mi][0] = f2tf32(ab[g * PADA + tq]);
        af[mi][1] = f2tf32(ab[(g + 8) * PADA + tq]);
        af[mi][2] = f2tf32(ab[g * PADA + tq + 4]);
        af[mi][3] = f2tf32(ab[(g + 8) * PADA + tq + 4]);
      }
#pragma unroll
      for (int ni = 0; ni < 8; ni++) {
        int col = wn + ni * 8 + g;
        const float* bp = &Bs[(s * BK + kk * 8 + tq) * PADB + col];
        uint32_t bf[2];
        bf[0] = f2tf32(bp[0]);
        bf[1] = f2tf32(bp[4 * PADB]);
#pragma unroll
        for (int mi = 0; mi < 2; mi++) mma_tf32(cc[mi][ni], af[mi], bf);
      }
    }
    __syncthreads();
  }

  const float* b2e = b2 + (size_t)e * HDIM;
#pragma unroll
  for (int mi = 0; mi < 2; mi++) {
#pragma unroll
    for (int rr = 0; rr < 2; rr++) {
      int lr = wm + mi * 16 + rr * 8 + g;
      int r = m0 + lr;
      if (r >= cnt) continue;
      int t = toks[lr];
      float w = wts[lr];
      float* orow = out + (size_t)t * HDIM;
#pragma unroll
      for (int ni = 0; ni < 8; ni++) {
        int c = n0 + wn + ni * 8 + (tq << 1);
        atomicAdd(&orow[c],     w * (cc[mi][ni][rr * 2 + 0] + b2e[c]));
        atomicAdd(&orow[c + 1], w * (cc[mi][ni][rr * 2 + 1] + b2e[c + 1]));
      }
    }
  }
}

// ---------------- launch ----------------

#define SMEM1_BYTES ((2 * BM * PADA + 4 * BK * PADB) * 4 + BM * 4)
#define SMEM2_BYTES ((2 * BM * PADA + 2 * BK * PADB) * 4 + BM * 8)

extern "C" void kernel_launch(void* const* d_in, const int* in_sizes, int n_in,
                              void* d_out, int out_size) {
  (void)in_sizes; (void)n_in; (void)out_size;
  const float* hs = (const float*)d_in[0];
  const float* rw = (const float*)d_in[1];
  const float* rb = (const float*)d_in[2];
  const float* w1 = (const float*)d_in[3];
  const float* b1 = (const float*)d_in[4];
  const float* w2 = (const float*)d_in[5];
  const float* b2 = (const float*)d_in[6];
  float* out = (float*)d_out;

  cudaMemsetAsync(out, 0, (size_t)TMAX * HDIM * sizeof(float));
  zero_cnt_kernel<<<1, 32>>>();
  router_kernel<<<TMAX / 8, 256>>>(hs, rw, rb);

  cudaFuncSetAttribute(gemm1_kernel, cudaFuncAttributeMaxDynamicSharedMemorySize, SMEM1_BYTES);
  cudaFuncSetAttribute(gemm2_kernel, cudaFuncAttributeMaxDynamicSharedMemorySize, SMEM2_BYTES);

  dim3 grid1(IDIM / BN, TMAX / BM, NEXP);
  gemm1_kernel<<<grid1, 256, SMEM1_BYTES>>>(hs, w1, b1);
  dim3 grid2(HDIM / BN, TMAX / BM, NEXP);
  gemm2_kernel<<<grid2, 256, SMEM2_BYTES>>>(w2, b2, out);
}